// round 16
// baseline (speedup 1.0000x reference)
#include <cuda_runtime.h>
#include <cuda_bf16.h>

#define N_NODES 100000
#define N_EDGES 600000
#define D 128
#define DIN 16
#define ND (N_NODES * D)

// ---------------- scratch (static __device__ arrays; no allocs) ----------------
__device__ float g_hnet[ND], g_hcell[ND];                 // projected features
__device__ float g_hs0[ND], g_hs1[ND], g_hs2[ND];         // h_src per relation
__device__ float g_bnet[ND], g_bcell[ND];                 // feat @ Wl1.T
__device__ float g_agg0[ND], g_agg1[ND], g_agg2[ND];      // normalized GAT outputs
__device__ float g_el[3][N_NODES], g_er[3][N_NODES];
__device__ float g_vr0[D], g_vr1[D], g_bvec[D];
__device__ int   g_cnt[3][N_NODES];
__device__ int   g_rowptr[3][N_NODES + 1];
__device__ int   g_cursor[3][N_NODES];
__device__ int   g_csrc[3][N_EDGES];
__device__ float g_cw[3][N_EDGES];

// ---------------- feature projection: h = x @ Wp.T  ([N,16] -> [N,128]) --------
__global__ __launch_bounds__(256) void proj_kernel(
    const float* __restrict__ x, const float* __restrict__ Wp,
    float* __restrict__ h) {
    __shared__ float Wt[DIN][D];          // Wt[j][k] = Wp[k][j]
    int tid = threadIdx.x;
    for (int i = tid; i < D * DIN; i += 256) {
        int k = i >> 4, j = i & 15;
        Wt[j][k] = Wp[i];
    }
    __syncthreads();
    int warp = tid >> 5, lane = tid & 31;
    int k0 = lane * 4;
    float4 w[16];
#pragma unroll
    for (int j = 0; j < 16; j++) w[j] = *(const float4*)&Wt[j][k0];

    int base = blockIdx.x * 32 + warp * 4;   // 4 nodes per warp
#pragma unroll
    for (int nn = 0; nn < 4; nn++) {
        int i = base + nn;
        if (i >= N_NODES) return;
        float xv = x[i * DIN + (lane & 15)];
        float4 acc = make_float4(0.f, 0.f, 0.f, 0.f);
#pragma unroll
        for (int j = 0; j < 16; j++) {
            float xj = __shfl_sync(0xffffffffu, xv, j);
            acc.x += xj * w[j].x; acc.y += xj * w[j].y;
            acc.z += xj * w[j].z; acc.w += xj * w[j].w;
        }
        *(float4*)&h[i * D + k0] = acc;
    }
}

// ---------------- attention vectors (3 blocks: vr0, vr1, bvec) ------------------
__global__ __launch_bounds__(128) void attnvec3_kernel(
    const float* __restrict__ Wg0, const float* __restrict__ ar0,
    const float* __restrict__ Wg1, const float* __restrict__ ar1,
    const float* __restrict__ Wl, const float* __restrict__ bias) {
    int k = threadIdx.x;
    int which = blockIdx.x;
    float s = 0.f;
    if (which == 0) {
#pragma unroll 8
        for (int j = 0; j < D; j++) s += Wg0[j * D + k] * ar0[j];
        g_vr0[k] = s;
    } else if (which == 1) {
#pragma unroll 8
        for (int j = 0; j < D; j++) s += Wg1[j * D + k] * ar1[j];
        g_vr1[k] = s;
    } else {
#pragma unroll 8
        for (int j = 0; j < D; j++) s += Wl[k * (2 * D) + D + j] * bias[j];
        g_bvec[k] = s;
    }
}

// ---------------- bf16x2 split-precision mma machinery ---------------------------
// fp32 x = hi + lo with hi = trunc-to-bf16(x), lo = trunc-to-bf16(x - hi).
// Split ONCE at staging; smem stores packed bf16 pairs (2 consecutive k per word)
// in separate hi/lo tiles. Inner loop = pure LDS + mma.m16n8k16.bf16 (3 products:
// lo*hi + hi*lo + hi*hi; dropped lo*lo ~ 2^-16 relative).
#define AW 68                      // words per smem row (64 data + 4 pad)
#define SMEM_TC ((2 * 64 * AW + 2 * 128 * AW) * 4)

__device__ __forceinline__ void split_pair(float x0, float x1,
                                           unsigned &hi, unsigned &lo) {
    unsigned u0 = __float_as_uint(x0), u1 = __float_as_uint(x1);
    unsigned h0 = u0 & 0xffff0000u, h1 = u1 & 0xffff0000u;
    hi = (h0 >> 16) | h1;
    float l0 = x0 - __uint_as_float(h0);
    float l1 = x1 - __uint_as_float(h1);
    lo = (__float_as_uint(l0) >> 16) | (__float_as_uint(l1) & 0xffff0000u);
}

__device__ __forceinline__ void unpack_pair(unsigned hi, unsigned lo,
                                            float &x0, float &x1) {
    x0 = __uint_as_float(hi << 16) + __uint_as_float(lo << 16);
    x1 = __uint_as_float(hi & 0xffff0000u) + __uint_as_float(lo & 0xffff0000u);
}

__device__ __forceinline__ void store_split4(unsigned* hrow, unsigned* lrow,
                                             int widx, float4 v) {
    unsigned h0, l0, h1, l1;
    split_pair(v.x, v.y, h0, l0);
    split_pair(v.z, v.w, h1, l1);
    hrow[widx] = h0; hrow[widx + 1] = h1;
    lrow[widx] = l0; lrow[widx + 1] = l1;
}

#define MMA_BF16(acc, a0, a1, a2, a3, b0, b1)                                   \
    asm volatile(                                                               \
        "mma.sync.aligned.m16n8k16.row.col.f32.bf16.bf16.f32 "                  \
        "{%0,%1,%2,%3},{%4,%5,%6,%7},{%8,%9},{%0,%1,%2,%3};"                    \
        : "+f"(acc[0]), "+f"(acc[1]), "+f"(acc[2]), "+f"(acc[3])                \
        : "r"(a0), "r"(a1), "r"(a2), "r"(a3), "r"(b0), "r"(b1))

// Each warp: 32 rows x 32 cols of the 64x128 output tile.
__device__ __forceinline__ void mma_tile_bf16(
    const unsigned* __restrict__ Ah, const unsigned* __restrict__ Al,
    const unsigned* __restrict__ Bh, const unsigned* __restrict__ Bl,
    float acc[2][4][4], int wm, int wn, int qr, int qc)
{
#pragma unroll
    for (int mt = 0; mt < 2; mt++)
#pragma unroll
        for (int nt = 0; nt < 4; nt++)
#pragma unroll
            for (int j = 0; j < 4; j++) acc[mt][nt][j] = 0.f;

#pragma unroll 2
    for (int kw = 0; kw < 64; kw += 8) {     // 16 k-values per iter (8 words)
        unsigned ah[2][4], al[2][4];
#pragma unroll
        for (int mt = 0; mt < 2; mt++) {
            int b0 = (wm * 32 + mt * 16 + qr) * AW + kw + qc;
            int b8 = b0 + 8 * AW;
            ah[mt][0] = Ah[b0];     al[mt][0] = Al[b0];
            ah[mt][1] = Ah[b8];     al[mt][1] = Al[b8];
            ah[mt][2] = Ah[b0 + 4]; al[mt][2] = Al[b0 + 4];
            ah[mt][3] = Ah[b8 + 4]; al[mt][3] = Al[b8 + 4];
        }
#pragma unroll
        for (int nt = 0; nt < 4; nt++) {
            int cb = (wn * 32 + nt * 8 + qr) * AW + kw + qc;
            unsigned bh0 = Bh[cb], bh1 = Bh[cb + 4];
            unsigned bl0 = Bl[cb], bl1 = Bl[cb + 4];
#pragma unroll
            for (int mt = 0; mt < 2; mt++) {
                MMA_BF16(acc[mt][nt], al[mt][0], al[mt][1], al[mt][2], al[mt][3], bh0, bh1);
                MMA_BF16(acc[mt][nt], ah[mt][0], ah[mt][1], ah[mt][2], ah[mt][3], bl0, bl1);
                MMA_BF16(acc[mt][nt], ah[mt][0], ah[mt][1], ah[mt][2], ah[mt][3], bh0, bh1);
            }
        }
    }
}

// ---------------- fused multi-weight GEMM: A staged once, up to 3 weights -------
__global__ __launch_bounds__(256, 2) void gemm_multi(
    const float* __restrict__ A,
    const float* __restrict__ W0, int ws0, float* __restrict__ C0,
    const float* __restrict__ W1, int ws1, float* __restrict__ C1,
    const float* __restrict__ W2, int ws2, float* __restrict__ C2,
    int nrows)
{
    extern __shared__ unsigned smu[];
    unsigned* Ah = smu;
    unsigned* Al = smu + 64 * AW;
    unsigned* Bh = smu + 2 * 64 * AW;
    unsigned* Bl = Bh + 128 * AW;
    int tid = threadIdx.x;
    int row0 = blockIdx.x * 64;

    const float* Wlist[3] = {W0, W1, W2};
    int wslist[3] = {ws0, ws1, ws2};
    float* Clist[3] = {C0, C1, C2};

    // stage A (split once)
    for (int i = tid; i < 64 * 32; i += 256) {
        int r = i >> 5, fc = (i & 31) * 4;
        int gr = row0 + r;
        float4 v = make_float4(0.f, 0.f, 0.f, 0.f);
        if (gr < nrows) v = *(const float4*)&A[(size_t)gr * D + fc];
        store_split4(Ah + r * AW, Al + r * AW, (i & 31) * 2, v);
    }
    // stage first W
    {
        const float* W = Wlist[0];
        int ws = wslist[0];
        for (int i = tid; i < 128 * 32; i += 256) {
            int r = i >> 5, fc = (i & 31) * 4;
            float4 v = *(const float4*)&W[(size_t)r * ws + fc];
            store_split4(Bh + r * AW, Bl + r * AW, (i & 31) * 2, v);
        }
    }
    __syncthreads();

    int lane = tid & 31, wid = tid >> 5;
    int wm = wid & 1, wn = wid >> 1;
    int qr = lane >> 2, qc = lane & 3;

#pragma unroll 1
    for (int s = 0; s < 3; s++) {
        if (!Wlist[s]) break;
        float acc[2][4][4];
        mma_tile_bf16(Ah, Al, Bh, Bl, acc, wm, wn, qr, qc);
        __syncthreads();   // all warps done reading Bs

        if (s + 1 < 3 && Wlist[s + 1]) {
            const float* W = Wlist[s + 1];
            int ws = wslist[s + 1];
            for (int i = tid; i < 128 * 32; i += 256) {
                int r = i >> 5, fc = (i & 31) * 4;
                float4 v = *(const float4*)&W[(size_t)r * ws + fc];
                store_split4(Bh + r * AW, Bl + r * AW, (i & 31) * 2, v);
            }
        }

        float* C = Clist[s];
#pragma unroll
        for (int mt = 0; mt < 2; mt++) {
#pragma unroll
            for (int half = 0; half < 2; half++) {
                int gr = row0 + wm * 32 + mt * 16 + qr + half * 8;
                if (gr >= nrows) continue;
#pragma unroll
                for (int nt = 0; nt < 4; nt++) {
                    int col = wn * 32 + nt * 8 + qc * 2;
                    float2 o = make_float2(acc[mt][nt][half * 2 + 0],
                                           acc[mt][nt][half * 2 + 1]);
                    *(float2*)&C[(size_t)gr * D + col] = o;
                }
            }
        }
        __syncthreads();
    }
}

// ---------------- fused output chain: nsteps x [relu(base+bvec+As@W.T)] --------
// Intermediates stay in the smem As tile (bf16x2 split) across steps.
__global__ __launch_bounds__(256, 2) void chain_tc(
    const float* __restrict__ preA, int initRelu,
    const float* __restrict__ addMid, int addIdx, int nsteps,
    const float* __restrict__ base, const float* __restrict__ bvec,
    const float* __restrict__ W,
    float* __restrict__ C, int nrows)
{
    extern __shared__ unsigned smu[];
    unsigned* Ah = smu;
    unsigned* Al = smu + 64 * AW;
    unsigned* Bh = smu + 2 * 64 * AW;
    unsigned* Bl = Bh + 128 * AW;
    int tid = threadIdx.x;
    int row0 = blockIdx.x * 64;

    // stage W (Wl2, row stride 2D)
    for (int i = tid; i < 128 * 32; i += 256) {
        int r = i >> 5, fc = (i & 31) * 4;
        float4 v = *(const float4*)&W[(size_t)r * (2 * D) + fc];
        store_split4(Bh + r * AW, Bl + r * AW, (i & 31) * 2, v);
    }
    // stage initial As
    for (int i = tid; i < 64 * 32; i += 256) {
        int r = i >> 5, fc = (i & 31) * 4;
        int gr = row0 + r;
        float4 v = make_float4(0.f, 0.f, 0.f, 0.f);
        if (gr < nrows) {
            v = *(const float4*)&preA[(size_t)gr * D + fc];
            if (initRelu) {
                float4 b = *(const float4*)&bvec[fc];
                v.x = fmaxf(v.x + b.x, 0.f); v.y = fmaxf(v.y + b.y, 0.f);
                v.z = fmaxf(v.z + b.z, 0.f); v.w = fmaxf(v.w + b.w, 0.f);
            }
        }
        store_split4(Ah + r * AW, Al + r * AW, (i & 31) * 2, v);
    }
    __syncthreads();

    int lane = tid & 31, wid = tid >> 5;
    int wm = wid & 1, wn = wid >> 1;
    int qr = lane >> 2, qc = lane & 3;

    float bv[4][2];
#pragma unroll
    for (int nt = 0; nt < 4; nt++) {
        int col = wn * 32 + nt * 8 + qc * 2;
        bv[nt][0] = bvec[col]; bv[nt][1] = bvec[col + 1];
    }

#pragma unroll 1
    for (int s = 0; s < nsteps; s++) {
        if (s == addIdx && addMid) {
            for (int i = tid; i < 64 * 32; i += 256) {
                int r = i >> 5, fc = (i & 31) * 4;
                int gr = row0 + r;
                if (gr < nrows) {
                    float4 a = *(const float4*)&addMid[(size_t)gr * D + fc];
                    int widx = (i & 31) * 2;
                    unsigned* hrow = Ah + r * AW;
                    unsigned* lrow = Al + r * AW;
                    float x0, x1, x2, x3;
                    unpack_pair(hrow[widx], lrow[widx], x0, x1);
                    unpack_pair(hrow[widx + 1], lrow[widx + 1], x2, x3);
                    store_split4(hrow, lrow, widx,
                                 make_float4(x0 + a.x, x1 + a.y, x2 + a.z, x3 + a.w));
                }
            }
            __syncthreads();
        }

        float acc[2][4][4];
        mma_tile_bf16(Ah, Al, Bh, Bl, acc, wm, wn, qr, qc);
        __syncthreads();   // done reading As; safe to overwrite

        bool last = (s == nsteps - 1);
#pragma unroll
        for (int mt = 0; mt < 2; mt++) {
#pragma unroll
            for (int half = 0; half < 2; half++) {
                int grl = wm * 32 + mt * 16 + qr + half * 8;
                int gr = row0 + grl;
                if (gr >= nrows) continue;
#pragma unroll
                for (int nt = 0; nt < 4; nt++) {
                    int col = wn * 32 + nt * 8 + qc * 2;
                    float2 b = *(const float2*)&base[(size_t)gr * D + col];
                    float v0 = fmaxf(acc[mt][nt][half * 2 + 0] + b.x + bv[nt][0], 0.f);
                    float v1 = fmaxf(acc[mt][nt][half * 2 + 1] + b.y + bv[nt][1], 0.f);
                    if (last) {
                        *(float2*)&C[(size_t)gr * D + col] = make_float2(v0, v1);
                    } else {
                        unsigned hi, lo;
                        split_pair(v0, v1, hi, lo);
                        int widx = grl * AW + (col >> 1);
                        Ah[widx] = hi; Al[widx] = lo;
                    }
                }
            }
        }
        __syncthreads();
    }
}

// ---------------- attention logits (el/er) per node -----------------------------
__global__ __launch_bounds__(256) void scores_net(
    const float* __restrict__ al1, const float* __restrict__ al2,
    const float* __restrict__ ar2) {
    int warp = threadIdx.x >> 5, lane = threadIdx.x & 31;
    int i = blockIdx.x * 8 + warp;
    if (i >= N_NODES) return;
    int o = i * D + lane * 4, c = lane * 4;
    float4 hn = *(const float4*)&g_hnet[o];
    float4 h1 = *(const float4*)&g_hs1[o];
    float4 h2 = *(const float4*)&g_hs2[o];
    float4 v0 = *(const float4*)&g_vr0[c];
    float4 a1 = *(const float4*)&al1[c];
    float4 a2 = *(const float4*)&al2[c];
    float4 r2 = *(const float4*)&ar2[c];
    float d0 = hn.x * v0.x + hn.y * v0.y + hn.z * v0.z + hn.w * v0.w;
    float d1 = h1.x * a1.x + h1.y * a1.y + h1.z * a1.z + h1.w * a1.w;
    float d2 = h2.x * a2.x + h2.y * a2.y + h2.z * a2.z + h2.w * a2.w;
    float d3 = h2.x * r2.x + h2.y * r2.y + h2.z * r2.z + h2.w * r2.w;
#pragma unroll
    for (int off = 16; off; off >>= 1) {
        d0 += __shfl_xor_sync(0xffffffffu, d0, off);
        d1 += __shfl_xor_sync(0xffffffffu, d1, off);
        d2 += __shfl_xor_sync(0xffffffffu, d2, off);
        d3 += __shfl_xor_sync(0xffffffffu, d3, off);
    }
    if (lane == 0) {
        g_er[0][i] = d0;
        g_el[1][i] = d1;
        g_el[2][i] = d2;
        g_er[2][i] = d3;
    }
}

__global__ __launch_bounds__(256) void scores_cell(const float* __restrict__ al0) {
    int warp = threadIdx.x >> 5, lane = threadIdx.x & 31;
    int i = blockIdx.x * 8 + warp;
    if (i >= N_NODES) return;
    int o = i * D + lane * 4, c = lane * 4;
    float4 h0 = *(const float4*)&g_hs0[o];
    float4 hc = *(const float4*)&g_hcell[o];
    float4 a0 = *(const float4*)&al0[c];
    float4 v1 = *(const float4*)&g_vr1[c];
    float d0 = h0.x * a0.x + h0.y * a0.y + h0.z * a0.z + h0.w * a0.w;
    float d1 = hc.x * v1.x + hc.y * v1.y + hc.z * v1.z + hc.w * v1.w;
#pragma unroll
    for (int off = 16; off; off >>= 1) {
        d0 += __shfl_xor_sync(0xffffffffu, d0, off);
        d1 += __shfl_xor_sync(0xffffffffu, d1, off);
    }
    if (lane == 0) {
        g_el[0][i] = d0;
        g_er[1][i] = d1;
    }
}

// ---------------- CSR build ------------------------------------------------------
__global__ __launch_bounds__(256) void count3_kernel(
    const int* __restrict__ dst0, const int* __restrict__ dst1,
    const int* __restrict__ dst2) {
    int e = blockIdx.x * blockDim.x + threadIdx.x;
    if (e >= N_EDGES) return;
    atomicAdd(&g_cnt[0][dst0[e]], 1);
    atomicAdd(&g_cnt[1][dst1[e]], 1);
    atomicAdd(&g_cnt[2][dst2[e]], 1);
}

__global__ __launch_bounds__(256) void scan_kernel() {
    int r = blockIdx.x;
    const int* cnt = g_cnt[r];
    int* rp = g_rowptr[r];
    __shared__ int part[256];
    int t = threadIdx.x;
    const int CH = 391;  // 256*391 >= 100000
    int base = t * CH;
    int s = 0;
    for (int j = 0; j < CH; j++) {
        int idx = base + j;
        if (idx < N_NODES) s += cnt[idx];
    }
    part[t] = s;
    __syncthreads();
    if (t == 0) {
        int acc = 0;
        for (int i = 0; i < 256; i++) { int v = part[i]; part[i] = acc; acc += v; }
        rp[N_NODES] = acc;
    }
    __syncthreads();
    int acc = part[t];
    for (int j = 0; j < CH; j++) {
        int idx = base + j;
        if (idx < N_NODES) { rp[idx] = acc; acc += cnt[idx]; }
    }
}

// fills for all 3 relations in one launch (grid.y = rel)
__global__ __launch_bounds__(256) void fill3_kernel(
    const int* __restrict__ src0, const int* __restrict__ dst0,
    const int* __restrict__ src1, const int* __restrict__ dst1,
    const int* __restrict__ src2, const int* __restrict__ dst2) {
    int rel = blockIdx.y;
    const int* src = (rel == 0) ? src0 : (rel == 1) ? src1 : src2;
    const int* dst = (rel == 0) ? dst0 : (rel == 1) ? dst1 : dst2;
    int e = blockIdx.x * blockDim.x + threadIdx.x;
    if (e >= N_EDGES) return;
    int s = src[e], d = dst[e];
    float x = g_el[rel][s] + g_er[rel][d];
    x = x > 0.f ? x : 0.2f * x;           // leaky_relu
    float w = __expf(x);
    int pos = atomicAdd(&g_cursor[rel][d], 1);
    int idx = g_rowptr[rel][d] + pos;
    g_csrc[rel][idx] = s;
    g_cw[rel][idx] = w;
}

// ---------------- aggregation, all rels, 4-way edge-unrolled gathers ------------
__global__ __launch_bounds__(256) void aggregate3_kernel(
    const float* __restrict__ hsA, const float* __restrict__ hsB,
    const float* __restrict__ hsC,
    float* __restrict__ aggA, float* __restrict__ aggB, float* __restrict__ aggC) {
    int rel = blockIdx.y;
    const float* hs = (rel == 0) ? hsA : (rel == 1) ? hsB : hsC;
    float* agg = (rel == 0) ? aggA : (rel == 1) ? aggB : aggC;
    int warp = threadIdx.x >> 5, lane = threadIdx.x & 31;
    int i = blockIdx.x * 8 + warp;
    if (i >= N_NODES) return;
    int start = g_rowptr[rel][i];
    int end = g_rowptr[rel][i + 1];
    const float4* hv = (const float4*)hs;
    const int* cs = g_csrc[rel];
    const float* cw = g_cw[rel];
    float4 acc = make_float4(0.f, 0.f, 0.f, 0.f);
    float wsum = 0.f;
    int t = start;
    for (; t + 4 <= end; t += 4) {
        int s0 = cs[t], s1 = cs[t + 1], s2 = cs[t + 2], s3 = cs[t + 3];
        float w0 = cw[t], w1 = cw[t + 1], w2 = cw[t + 2], w3 = cw[t + 3];
        float4 v0 = hv[(size_t)s0 * 32 + lane];
        float4 v1 = hv[(size_t)s1 * 32 + lane];
        float4 v2 = hv[(size_t)s2 * 32 + lane];
        float4 v3 = hv[(size_t)s3 * 32 + lane];
        acc.x += w0 * v0.x + w1 * v1.x + w2 * v2.x + w3 * v3.x;
        acc.y += w0 * v0.y + w1 * v1.y + w2 * v2.y + w3 * v3.y;
        acc.z += w0 * v0.z + w1 * v1.z + w2 * v2.z + w3 * v3.z;
        acc.w += w0 * v0.w + w1 * v1.w + w2 * v2.w + w3 * v3.w;
        wsum += w0 + w1 + w2 + w3;
    }
    for (; t < end; t++) {
        int s = cs[t];
        float w = cw[t];
        float4 v = hv[(size_t)s * 32 + lane];
        acc.x += w * v.x; acc.y += w * v.y; acc.z += w * v.z; acc.w += w * v.w;
        wsum += w;
    }
    float4 o = make_float4(0.f, 0.f, 0.f, 0.f);
    if (end > start) {
        float inv = 1.f / wsum;
        o = make_float4(acc.x * inv, acc.y * inv, acc.z * inv, acc.w * inv);
    }
    ((float4*)agg)[(size_t)i * 32 + lane] = o;
}

// ---------------- host orchestration (3-stream fork/join DAG) -------------------
extern "C" void kernel_launch(void* const* d_in, const int* in_sizes, int n_in,
                              void* d_out, int out_size) {
    const float* x_net   = (const float*)d_in[0];
    const float* x_cell  = (const float*)d_in[1];
    const float* Wp_net  = (const float*)d_in[2];
    const float* Wp_cell = (const float*)d_in[3];
    const float* Wg0 = (const float*)d_in[4];
    const float* al0 = (const float*)d_in[5];
    const float* ar0 = (const float*)d_in[6];
    const float* Wg1 = (const float*)d_in[7];
    const float* al1 = (const float*)d_in[8];
    const float* ar1 = (const float*)d_in[9];
    const float* Wg2 = (const float*)d_in[10];
    const float* al2 = (const float*)d_in[11];
    const float* ar2 = (const float*)d_in[12];
    const float* Wl   = (const float*)d_in[13];
    const float* bias = (const float*)d_in[14];
    const int* src0 = (const int*)d_in[15];
    const int* dst0 = (const int*)d_in[16];
    const int* src1 = (const int*)d_in[17];
    const int* dst1 = (const int*)d_in[18];
    const int* src2 = (const int*)d_in[19];
    const int* dst2 = (const int*)d_in[20];
    float* out = (float*)d_out;

    float *hnet, *hcell, *hs0, *hs1, *hs2, *bnet, *bcell;
    float *agg0, *agg1, *agg2, *bvec;
    int *cnt, *cursor;
    cudaGetSymbolAddress((void**)&hnet,  g_hnet);
    cudaGetSymbolAddress((void**)&hcell, g_hcell);
    cudaGetSymbolAddress((void**)&hs0,   g_hs0);
    cudaGetSymbolAddress((void**)&hs1,   g_hs1);
    cudaGetSymbolAddress((void**)&hs2,   g_hs2);
    cudaGetSymbolAddress((void**)&bnet,  g_bnet);
    cudaGetSymbolAddress((void**)&bcell, g_bcell);
    cudaGetSymbolAddress((void**)&agg0,  g_agg0);
    cudaGetSymbolAddress((void**)&agg1,  g_agg1);
    cudaGetSymbolAddress((void**)&agg2,  g_agg2);
    cudaGetSymbolAddress((void**)&bvec,  g_bvec);
    cudaGetSymbolAddress((void**)&cnt,   g_cnt);
    cudaGetSymbolAddress((void**)&cursor, g_cursor);

    static cudaStream_t sA = 0, sB = 0, sC = 0;
    static cudaEvent_t evFork, eC0, eA1, eB1, eC1, eAgg, eA3, eB3;
    static int init_done = 0;
    if (!init_done) {
        cudaFuncSetAttribute(gemm_multi, cudaFuncAttributeMaxDynamicSharedMemorySize, SMEM_TC);
        cudaFuncSetAttribute(chain_tc,   cudaFuncAttributeMaxDynamicSharedMemorySize, SMEM_TC);
        cudaStreamCreateWithFlags(&sA, cudaStreamNonBlocking);
        cudaStreamCreateWithFlags(&sB, cudaStreamNonBlocking);
        cudaStreamCreateWithFlags(&sC, cudaStreamNonBlocking);
        cudaEventCreateWithFlags(&evFork, cudaEventDisableTiming);
        cudaEventCreateWithFlags(&eC0, cudaEventDisableTiming);
        cudaEventCreateWithFlags(&eA1, cudaEventDisableTiming);
        cudaEventCreateWithFlags(&eB1, cudaEventDisableTiming);
        cudaEventCreateWithFlags(&eC1, cudaEventDisableTiming);
        cudaEventCreateWithFlags(&eAgg, cudaEventDisableTiming);
        cudaEventCreateWithFlags(&eA3, cudaEventDisableTiming);
        cudaEventCreateWithFlags(&eB3, cudaEventDisableTiming);
        init_done = 1;
    }

    const int GN = (N_NODES + 7) / 8;        // warp-per-node kernels
    const int GP = (N_NODES + 31) / 32;      // proj: 4 nodes/warp
    const int GT = (N_NODES + 63) / 64;      // tensor gemm tiles (BM=64)
    const int GE = (N_EDGES + 255) / 256;
    const float* Wl2 = Wl + D;               // Wl[:, 128:], row stride 2*D

    // ---- fork immediately (no serial prefix) ----
    cudaEventRecord(evFork, 0);
    cudaStreamWaitEvent(sA, evFork, 0);
    cudaStreamWaitEvent(sB, evFork, 0);
    cudaStreamWaitEvent(sC, evFork, 0);

    // ---- branch C: attention vectors + CSR skeleton ----
    attnvec3_kernel<<<3, 128, 0, sC>>>(Wg0, ar0, Wg1, ar1, Wl, bias);
    cudaEventRecord(eC0, sC);
    cudaMemsetAsync(cnt,    0, sizeof(int) * 3 * N_NODES, sC);
    cudaMemsetAsync(cursor, 0, sizeof(int) * 3 * N_NODES, sC);
    count3_kernel<<<GE, 256, 0, sC>>>(dst0, dst1, dst2);
    scan_kernel<<<3, 256, 0, sC>>>();
    cudaEventRecord(eC1, sC);

    // ---- branch A: net-side features (fused 3-weight GEMM) ----
    proj_kernel<<<GP, 256, 0, sA>>>(x_net, Wp_net, hnet);
    gemm_multi<<<GT, 256, SMEM_TC, sA>>>(hnet,
        Wg1, D, hs1, Wg2, D, hs2, Wl, 2 * D, bnet, N_NODES);
    cudaStreamWaitEvent(sA, eC0, 0);
    scores_net<<<GN, 256, 0, sA>>>(al1, al2, ar2);
    cudaEventRecord(eA1, sA);

    // ---- branch B: cell-side features (fused 2-weight GEMM) ----
    proj_kernel<<<GP, 256, 0, sB>>>(x_cell, Wp_cell, hcell);
    gemm_multi<<<GT, 256, SMEM_TC, sB>>>(hcell,
        Wg0, D, hs0, Wl, 2 * D, bcell, nullptr, 0, nullptr, N_NODES);
    cudaStreamWaitEvent(sB, eC0, 0);
    scores_cell<<<GN, 256, 0, sB>>>(al0);
    cudaEventRecord(eB1, sB);

    // ---- join J1 on sA: scores + CSR skeleton complete ----
    cudaStreamWaitEvent(sA, eB1, 0);
    cudaStreamWaitEvent(sA, eC1, 0);

    // ---- single big fill + single big aggregate (device-saturating) ----
    dim3 gfill(GE, 3);
    fill3_kernel<<<gfill, 256, 0, sA>>>(src0, dst0, src1, dst1, src2, dst2);
    dim3 gagg(GN, 3);
    aggregate3_kernel<<<gagg, 256, 0, sA>>>(hs0, hs1, hs2, agg0, agg1, agg2);
    cudaEventRecord(eAgg, sA);

    // ---- output chains in parallel ----
    chain_tc<<<GT, 256, SMEM_TC, sA>>>(agg0, 0, agg2, 2, 3,
                                       bnet, bvec, Wl2, out, N_NODES);
    cudaEventRecord(eA3, sA);

    cudaStreamWaitEvent(sB, eAgg, 0);
    chain_tc<<<GT, 256, SMEM_TC, sB>>>(bcell, 1, agg1, 0, 2,
                                       bcell, bvec, Wl2, out + ND, N_NODES);
    cudaEventRecord(eB3, sB);

    // ---- join back to origin stream ----
    cudaStreamWaitEvent(0, eA3, 0);
    cudaStreamWaitEvent(0, eB3, 0);
}